// round 8
// baseline (speedup 1.0000x reference)
#include <cuda_runtime.h>
#include <cuda_fp16.h>
#include <cstdint>

// Problem constants
#define BB 4
#define SS 2048
#define DD 512
#define HH 8
#define DK 64
#define DV 64
#define BS (BB * SS)          // 8192 rows total
#define QT3 128               // query rows per attention block
#define NQT3 (SS / QT3)       // 16 q-tiles per batch

// Scratch (device globals: no allocations allowed)
__device__ unsigned g_q2[BS * DK / 2];    // half2: (q@Wq+bq)*0.125, [row][32 u32]
__device__ unsigned g_k2[BS * DK / 2];    // half2: k, [row][32 u32]
__device__ __half   g_vT[BB * DV * SS];   // half, per-batch transposed [dim][seq]
__device__ unsigned g_o2[BS * DV / 2];    // half2: attention out, [row][32 u32]
__device__ unsigned g_woT2[DD * DV / 2];  // half2: woeff^T [n][k], [512][32 u32]

// ---------------------------------------------------------------------------
// helpers
// ---------------------------------------------------------------------------
__device__ __forceinline__ float f2tff(float f) {
    unsigned u;
    asm("cvt.rna.tf32.f32 %0, %1;" : "=r"(u) : "f"(f));
    return __uint_as_float(u);
}
// D(16x8,f32) += A(16x8,tf32,row) * B(8x8,tf32,col)
__device__ __forceinline__ void mma8(float* c, unsigned a0, unsigned a1,
                                     unsigned a2, unsigned a3,
                                     unsigned b0, unsigned b1) {
    asm volatile(
        "mma.sync.aligned.m16n8k8.row.col.f32.tf32.tf32.f32 "
        "{%0,%1,%2,%3}, {%4,%5,%6,%7}, {%8,%9}, {%0,%1,%2,%3};\n"
        : "+f"(c[0]), "+f"(c[1]), "+f"(c[2]), "+f"(c[3])
        : "r"(a0), "r"(a1), "r"(a2), "r"(a3), "r"(b0), "r"(b1));
}
// D(16x8,f32) += A(16x16,f16,row) * B(16x8,f16,col)
__device__ __forceinline__ void mma16(float* c, unsigned a0, unsigned a1,
                                      unsigned a2, unsigned a3,
                                      unsigned b0, unsigned b1) {
    asm volatile(
        "mma.sync.aligned.m16n8k16.row.col.f32.f16.f16.f32 "
        "{%0,%1,%2,%3}, {%4,%5,%6,%7}, {%8,%9}, {%0,%1,%2,%3};\n"
        : "+f"(c[0]), "+f"(c[1]), "+f"(c[2]), "+f"(c[3])
        : "r"(a0), "r"(a1), "r"(a2), "r"(a3), "r"(b0), "r"(b1));
}
__device__ __forceinline__ unsigned packh2(float hi, float lo) {
    unsigned d;
    asm("cvt.rn.f16x2.f32 %0, %1, %2;" : "=r"(d) : "f"(hi), "f"(lo));
    return d;
}
__device__ __forceinline__ unsigned ex2h2(unsigned x) {
    unsigned d;
    asm("ex2.approx.f16x2 %0, %1;" : "=r"(d) : "r"(x));
    return d;
}
__device__ __forceinline__ void cpa16(uint32_t saddr, const void* gaddr) {
    asm volatile("cp.async.cg.shared.global [%0], [%1], 16;\n"
                 :: "r"(saddr), "l"(gaddr));
}
__device__ __forceinline__ void cpa_commit() {
    asm volatile("cp.async.commit_group;\n");
}
__device__ __forceinline__ void cpa_wait0() {
    asm volatile("cp.async.wait_group 0;\n");
}
__device__ __forceinline__ void cpa_wait1() {
    asm volatile("cp.async.wait_group 1;\n");
}

// ---------------------------------------------------------------------------
// Kernel 1: fold Wo over identical heads -> half, transposed [n][k]
// ---------------------------------------------------------------------------
__global__ void woeff_kernel(const float* __restrict__ Wo) {
    int idx = blockIdx.x * blockDim.x + threadIdx.x;   // 64*512
    if (idx < DV * DD) {
        int r = idx >> 9;          // k (0..63)
        int c = idx & 511;         // n (0..511)
        float s = 0.f;
#pragma unroll
        for (int h = 0; h < HH; ++h) s += Wo[((h << 6) + r) * DD + c];
        ((__half*)g_woT2)[c * 64 + r] = __float2half(s);
    }
}

// ---------------------------------------------------------------------------
// Kernel 2: fused projections on tf32 tensor cores; epilogue emits fp16.
// blockIdx.y: 0 -> q (scaled 0.125); 1 -> k AND vT (shared A tile).
// 128 threads = 4 warps.
// ---------------------------------------------------------------------------
__global__ void __launch_bounds__(128) proj_mma_kernel(
    const float* __restrict__ query, const float* __restrict__ key,
    const float* __restrict__ Wq, const float* __restrict__ bq,
    const float* __restrict__ Wk, const float* __restrict__ bk,
    const float* __restrict__ Wv, const float* __restrict__ bv)
{
    const int fused = blockIdx.y;           // 0: q, 1: k+v
    const float* A  = fused ? key : query;
    const int m0 = blockIdx.x * 64;

    __shared__ float As[64][36];
    __shared__ float W1s[32][72];
    __shared__ float W2s[32][72];

    const int t    = threadIdx.x;
    const int w    = t >> 5;
    const int lane = t & 31;
    const int g    = lane >> 2;
    const int t4   = lane & 3;

    float c1[8][4] = {};
    float c2[8][4] = {};

    for (int kk = 0; kk < DD; kk += 32) {
        __syncthreads();
#pragma unroll
        for (int u = 0; u < 4; ++u) {
            int fi = t + u * 128;
            int r  = fi >> 3;
            int c4 = (fi & 7) << 2;
            float4 a4 = *(const float4*)(A + (size_t)(m0 + r) * DD + kk + c4);
            As[r][c4 + 0] = f2tff(a4.x);
            As[r][c4 + 1] = f2tff(a4.y);
            As[r][c4 + 2] = f2tff(a4.z);
            As[r][c4 + 3] = f2tff(a4.w);
        }
#pragma unroll
        for (int u = 0; u < 4; ++u) {
            int fi = t + u * 128;
            int r  = fi >> 4;
            int c4 = (fi & 15) << 2;
            const float* Wa = fused ? Wk : Wq;
            float4 w4 = *(const float4*)(Wa + (size_t)(kk + r) * DK + c4);
            W1s[r][c4 + 0] = f2tff(w4.x);
            W1s[r][c4 + 1] = f2tff(w4.y);
            W1s[r][c4 + 2] = f2tff(w4.z);
            W1s[r][c4 + 3] = f2tff(w4.w);
            if (fused) {
                float4 v4 = *(const float4*)(Wv + (size_t)(kk + r) * DK + c4);
                W2s[r][c4 + 0] = f2tff(v4.x);
                W2s[r][c4 + 1] = f2tff(v4.y);
                W2s[r][c4 + 2] = f2tff(v4.z);
                W2s[r][c4 + 3] = f2tff(v4.w);
            }
        }
        __syncthreads();

#pragma unroll
        for (int kt = 0; kt < 4; ++kt) {
            unsigned a0 = __float_as_uint(As[w * 16 + g    ][kt * 8 + t4    ]);
            unsigned a1 = __float_as_uint(As[w * 16 + g + 8][kt * 8 + t4    ]);
            unsigned a2 = __float_as_uint(As[w * 16 + g    ][kt * 8 + t4 + 4]);
            unsigned a3 = __float_as_uint(As[w * 16 + g + 8][kt * 8 + t4 + 4]);
#pragma unroll
            for (int nt = 0; nt < 8; ++nt) {
                unsigned b0 = __float_as_uint(W1s[kt * 8 + t4    ][nt * 8 + g]);
                unsigned b1 = __float_as_uint(W1s[kt * 8 + t4 + 4][nt * 8 + g]);
                mma8(c1[nt], a0, a1, a2, a3, b0, b1);
            }
            if (fused) {
#pragma unroll
                for (int nt = 0; nt < 8; ++nt) {
                    unsigned b0 = __float_as_uint(W2s[kt * 8 + t4    ][nt * 8 + g]);
                    unsigned b1 = __float_as_uint(W2s[kt * 8 + t4 + 4][nt * 8 + g]);
                    mma8(c2[nt], a0, a1, a2, a3, b0, b1);
                }
            }
        }
    }

    // epilogue -> fp16
    const int r0 = m0 + w * 16 + g;            // global row
    const float* bias1 = fused ? bk : bq;
    unsigned* out1     = fused ? g_k2 : g_q2;
    const float sc     = fused ? 1.0f : 0.125f;
#pragma unroll
    for (int nt = 0; nt < 8; ++nt) {
        int cc = nt * 8 + 2 * t4;
        float b0 = bias1[cc], b1 = bias1[cc + 1];
        out1[r0 * 32 + (cc >> 1)] =
            packh2((c1[nt][1] + b1) * sc, (c1[nt][0] + b0) * sc);
        out1[(r0 + 8) * 32 + (cc >> 1)] =
            packh2((c1[nt][3] + b1) * sc, (c1[nt][2] + b0) * sc);
    }
    if (fused) {
        const int bq_ = r0 >> 11;              // batch
        const int sq  = r0 & 2047;             // seq within batch
#pragma unroll
        for (int nt = 0; nt < 8; ++nt) {
            int cc = nt * 8 + 2 * t4;
            float b0 = bv[cc], b1 = bv[cc + 1];
            __half* base0 = g_vT + ((size_t)bq_ * 64 + cc) * SS;
            __half* base1 = g_vT + ((size_t)bq_ * 64 + cc + 1) * SS;
            base0[sq]     = __float2half(c2[nt][0] + b0);
            base1[sq]     = __float2half(c2[nt][1] + b1);
            base0[sq + 8] = __float2half(c2[nt][2] + b0);
            base1[sq + 8] = __float2half(c2[nt][3] + b1);
        }
    }
}

// ---------------------------------------------------------------------------
// Kernel 3: causal flash attention, fp16 tensor cores.
// Block = 128 q-rows, 256 threads = 8 warps; warp w: rows w*16..+15 x all keys.
// K tile [key][dim] half (pitch 36 u32); V^T tile [dim][key] half (pitch 36).
// ex2.approx.f16x2 output doubles as PV A-fragments; row sums via ones-MMA.
// ---------------------------------------------------------------------------
#define P32 36
__global__ void __launch_bounds__(256) attn_kernel() {
    __shared__ unsigned kb[2][64 * P32];
    __shared__ unsigned vb[2][64 * P32];

    const int b  = blockIdx.x & 3;
    const int it = (NQT3 - 1) - (blockIdx.x >> 2);   // longest-first

    const int t    = threadIdx.x;
    const int w    = t >> 5;          // 0..7
    const int lane = t & 31;
    const int g    = lane >> 2;
    const int t4   = lane & 3;
    const int r0   = w * 16 + g;      // 0..127
    const unsigned FULL = 0xffffffffu;
    const unsigned ONES2 = 0x3C003C00u;   // half2 {1.0, 1.0}
    const float L2E = 1.44269504f;

    // ---- Q A-fragments straight from gmem (once per block) ----
    const unsigned* qg = g_q2 + (size_t)(b * SS + it * QT3) * 32;
    unsigned aq[4][4];
#pragma unroll
    for (int kt = 0; kt < 4; ++kt) {
        aq[kt][0] = qg[(r0    ) * 32 + kt * 8 + t4    ];
        aq[kt][1] = qg[(r0 + 8) * 32 + kt * 8 + t4    ];
        aq[kt][2] = qg[(r0    ) * 32 + kt * 8 + t4 + 4];
        aq[kt][3] = qg[(r0 + 8) * 32 + kt * 8 + t4 + 4];
    }

    const int ntiles = 2 * (it + 1);
    const __half* kgp = (const __half*)g_k2 + (size_t)(b * SS) * DK;
    const __half* vgp = g_vT + (size_t)b * 64 * SS;
    const int qpos0 = it * QT3 + r0;

    // prologue: tile 0 -> buffer 0 (2 K-chunks + 2 V-chunks per thread)
    {
        uint32_t kba = (uint32_t)__cvta_generic_to_shared(&kb[0][0]);
        uint32_t vba = (uint32_t)__cvta_generic_to_shared(&vb[0][0]);
#pragma unroll
        for (int u = 0; u < 2; ++u) {
            int fi = t + u * 256;       // 512 chunks of 16B
            int r  = fi >> 3;
            int c  = fi & 7;
            cpa16(kba + (r * P32 + c * 4) * 4, kgp + (size_t)r * DK + c * 8);
            cpa16(vba + (r * P32 + c * 4) * 4, vgp + (size_t)r * SS + c * 8);
        }
        cpa_commit();
    }

    float o[8][4] = {};
    float mrow0 = -1e30f, mrow1 = -1e30f;
    float lrow0 = 0.f,    lrow1 = 0.f;

    for (int jt = 0; jt < ntiles; ++jt) {
        const int cur = jt & 1;
        if (jt > 0) __syncthreads();   // frees buf[(jt+1)&1]
        if (jt + 1 < ntiles) {
            const int nxt = (jt + 1) & 1;
            uint32_t kba = (uint32_t)__cvta_generic_to_shared(&kb[nxt][0]);
            uint32_t vba = (uint32_t)__cvta_generic_to_shared(&vb[nxt][0]);
            const __half* kgn = kgp + (size_t)(jt + 1) * 64 * DK;
            const __half* vgn = vgp + (size_t)(jt + 1) * 64;
#pragma unroll
            for (int u = 0; u < 2; ++u) {
                int fi = t + u * 256;
                int r  = fi >> 3;
                int c  = fi & 7;
                cpa16(kba + (r * P32 + c * 4) * 4, kgn + (size_t)r * DK + c * 8);
                cpa16(vba + (r * P32 + c * 4) * 4, vgn + (size_t)r * SS + c * 8);
            }
            cpa_commit();
            cpa_wait1();
        } else {
            cpa_wait0();
        }
        __syncthreads();

        const unsigned* kc = &kb[cur][0];
        const unsigned* vc = &vb[cur][0];

        // ---- S = Q K^T : 4 k-groups x 8 key-groups ----
        float c[8][4] = {};
#pragma unroll
        for (int kt = 0; kt < 4; ++kt) {
#pragma unroll
            for (int nt = 0; nt < 8; ++nt) {
                unsigned b0 = kc[(nt * 8 + g) * P32 + kt * 8 + t4    ];
                unsigned b1 = kc[(nt * 8 + g) * P32 + kt * 8 + t4 + 4];
                mma16(c[nt], aq[kt][0], aq[kt][1], aq[kt][2], aq[kt][3], b0, b1);
            }
        }

        // ---- causal mask (last two tiles can intersect the diagonal) ----
        if (jt >= ntiles - 2) {
#pragma unroll
            for (int nt = 0; nt < 8; ++nt) {
                int kp = jt * 64 + nt * 8 + 2 * t4;
                if (kp     > qpos0)     c[nt][0] = -1e30f;
                if (kp + 1 > qpos0)     c[nt][1] = -1e30f;
                if (kp     > qpos0 + 8) c[nt][2] = -1e30f;
                if (kp + 1 > qpos0 + 8) c[nt][3] = -1e30f;
            }
        }

        // ---- warp-local online softmax (quad reduce for max) ----
        float rm0 = -1e30f, rm1 = -1e30f;
#pragma unroll
        for (int nt = 0; nt < 8; ++nt) {
            rm0 = fmaxf(rm0, fmaxf(c[nt][0], c[nt][1]));
            rm1 = fmaxf(rm1, fmaxf(c[nt][2], c[nt][3]));
        }
        rm0 = fmaxf(rm0, __shfl_xor_sync(FULL, rm0, 1));
        rm0 = fmaxf(rm0, __shfl_xor_sync(FULL, rm0, 2));
        rm1 = fmaxf(rm1, __shfl_xor_sync(FULL, rm1, 1));
        rm1 = fmaxf(rm1, __shfl_xor_sync(FULL, rm1, 2));

        float nm0 = fmaxf(mrow0, rm0);
        float nm1 = fmaxf(mrow1, rm1);
        float corr0 = __expf(mrow0 - nm0); mrow0 = nm0;
        float corr1 = __expf(mrow1 - nm1); mrow1 = nm1;
        float nl0 = nm0 * L2E;
        float nl1 = nm1 * L2E;

#pragma unroll
        for (int nt = 0; nt < 8; ++nt) {
            o[nt][0] *= corr0; o[nt][1] *= corr0;
            o[nt][2] *= corr1; o[nt][3] *= corr1;
        }

        // ---- exp (f16x2) -> PV A-frags + ones-MMA row sums + PV MMA ----
        float ds[4] = {0.f, 0.f, 0.f, 0.f};
#pragma unroll
        for (int kt = 0; kt < 4; ++kt) {
            int ne = 2 * kt, no_ = 2 * kt + 1;
            unsigned aP0 = ex2h2(packh2(c[ne ][1] * L2E - nl0, c[ne ][0] * L2E - nl0));
            unsigned aP1 = ex2h2(packh2(c[ne ][3] * L2E - nl1, c[ne ][2] * L2E - nl1));
            unsigned aP2 = ex2h2(packh2(c[no_][1] * L2E - nl0, c[no_][0] * L2E - nl0));
            unsigned aP3 = ex2h2(packh2(c[no_][3] * L2E - nl1, c[no_][2] * L2E - nl1));
            mma16(ds, aP0, aP1, aP2, aP3, ONES2, ONES2);
#pragma unroll
            for (int nt = 0; nt < 8; ++nt) {
                unsigned b0 = vc[(nt * 8 + g) * P32 + kt * 8 + t4    ];
                unsigned b1 = vc[(nt * 8 + g) * P32 + kt * 8 + t4 + 4];
                mma16(o[nt], aP0, aP1, aP2, aP3, b0, b1);
            }
        }
        lrow0 = lrow0 * corr0 + ds[0];
        lrow1 = lrow1 * corr1 + ds[2];
    }

    // ---- epilogue: o = acc / l -> half2 for outgemm ----
    float inv0 = 1.f / lrow0;
    float inv1 = 1.f / lrow1;
    unsigned* og = g_o2 + (size_t)(b * SS + it * QT3 + w * 16) * 32;
#pragma unroll
    for (int nt = 0; nt < 8; ++nt) {
        int dc2 = nt * 4 + t4;    // u32 column
        og[g * 32 + dc2]       = packh2(o[nt][1] * inv0, o[nt][0] * inv0);
        og[(g + 8) * 32 + dc2] = packh2(o[nt][3] * inv1, o[nt][2] * inv1);
    }
}

// ---------------------------------------------------------------------------
// Kernel 4: out[8192,512] = o[8192,64] @ woeff[64,512] + bo  (fp16 mma)
// 256 threads = 8 warps; block = 64 rows x 128 cols; K = 64 single shot.
// warp w: rows (w&3)*16, cols (w>>2)*64.
// ---------------------------------------------------------------------------
__global__ void __launch_bounds__(256) outgemm_mma_kernel(
    const float* __restrict__ bo, float* __restrict__ out)
{
    const int m0 = blockIdx.x * 64;
    const int n0 = blockIdx.y * 128;

    __shared__ unsigned Ao[64 * P32];     // o tile [row][k-half2], pitch 36
    __shared__ unsigned Ws[128 * P32];    // woT tile [n][k-half2], pitch 36

    const int t    = threadIdx.x;
    const int w    = t >> 5;
    const int lane = t & 31;
    const int g    = lane >> 2;
    const int t4   = lane & 3;
    const int rw   = (w & 3) * 16;
    const int cw   = (w >> 2) * 64;

    // load o tile: 64 rows x 32 u32 = 512 float4 (2/thread)
#pragma unroll
    for (int u = 0; u < 2; ++u) {
        int fi = t + u * 256;
        int r  = fi >> 3;
        int c  = (fi & 7) << 2;
        *(float4*)&Ao[r * P32 + c] = *(const float4*)(g_o2 + (size_t)(m0 + r) * 32 + c);
    }
    // load woT tile: 128 rows x 32 u32 = 1024 float4 (4/thread)
#pragma unroll
    for (int u = 0; u < 4; ++u) {
        int fi = t + u * 256;
        int r  = fi >> 3;
        int c  = (fi & 7) << 2;
        *(float4*)&Ws[r * P32 + c] = *(const float4*)(g_woT2 + (size_t)(n0 + r) * 32 + c);
    }
    __syncthreads();

    float acc[8][4] = {};
#pragma unroll
    for (int kt = 0; kt < 4; ++kt) {
        unsigned a0 = Ao[(rw + g    ) * P32 + kt * 8 + t4    ];
        unsigned a1 = Ao[(rw + g + 8) * P32 + kt * 8 + t4    ];
        unsigned a2 = Ao[(rw + g    ) * P32 + kt * 8 + t4 + 4];
        unsigned a3 = Ao[(rw + g + 8) * P32 + kt * 8 + t4 + 4];
#pragma unroll
        for (int nt = 0; nt < 8; ++nt) {
            unsigned b0 = Ws[(cw + nt * 8 + g) * P32 + kt * 8 + t4    ];
            unsigned b1 = Ws[(cw + nt * 8 + g) * P32 + kt * 8 + t4 + 4];
            mma16(acc[nt], a0, a1, a2, a3, b0, b1);
        }
    }

    const int row0 = m0 + rw + g;
#pragma unroll
    for (int nt = 0; nt < 8; ++nt) {
        int cc = n0 + cw + nt * 8 + 2 * t4;
        float b0 = bo[cc], b1 = bo[cc + 1];
        *(float2*)(out + (size_t)row0 * DD + cc)       = make_float2(acc[nt][0] + b0, acc[nt][1] + b1);
        *(float2*)(out + (size_t)(row0 + 8) * DD + cc) = make_float2(acc[nt][2] + b0, acc[nt][3] + b1);
    }
}

// ---------------------------------------------------------------------------
// Launch
// Inputs: 0 query, 1 key, 2 value(unused), 3 Wq, 4 bq, 5 Wk, 6 bk,
//         7 Wv, 8 bv, 9 Wo, 10 bo
// ---------------------------------------------------------------------------
extern "C" void kernel_launch(void* const* d_in, const int* in_sizes, int n_in,
                              void* d_out, int out_size)
{
    const float* query = (const float*)d_in[0];
    const float* key   = (const float*)d_in[1];
    const float* Wq    = (const float*)d_in[3];
    const float* bq    = (const float*)d_in[4];
    const float* Wk    = (const float*)d_in[5];
    const float* bk    = (const float*)d_in[6];
    const float* Wv    = (const float*)d_in[7];
    const float* bv    = (const float*)d_in[8];
    const float* Wo    = (const float*)d_in[9];
    const float* bo    = (const float*)d_in[10];
    float* out = (float*)d_out;

    woeff_kernel<<<64, 512>>>(Wo);
    proj_mma_kernel<<<dim3(BS / 64, 2), 128>>>(query, key, Wq, bq, Wk, bk, Wv, bv);
    attn_kernel<<<BB * NQT3, 256>>>();
    outgemm_mma_kernel<<<dim3(BS / 64, DD / 128), 256>>>(bo, out);
}

// round 9
// speedup vs baseline: 1.3193x; 1.3193x over previous
#include <cuda_runtime.h>
#include <cuda_fp16.h>
#include <cstdint>

// Problem constants
#define BB 4
#define SS 2048
#define DD 512
#define HH 8
#define DK 64
#define DV 64
#define BS (BB * SS)          // 8192 rows total
#define QT2 64                // query rows per attention block
#define NQT2 (SS / QT2)       // 32 q-tiles per batch

// Scratch (device globals: no allocations allowed)
__device__ unsigned g_q2[BS * DK / 2];    // half2: (q@Wq+bq)*0.125, [row][32 u32]
__device__ unsigned g_k2[BS * DK / 2];    // half2: k, [row][32 u32]
__device__ __half   g_vT[BB * DV * SS];   // half, per-batch transposed [dim][seq]
__device__ unsigned g_o2[BS * DV / 2];    // half2: merged attention out
__device__ unsigned g_woT2[DD * DV / 2];  // half2: woeff^T [n][k], [512][32 u32]
// split-KV partials (fp32, unnormalized)
__device__ float    g_pacc[2 * BS * DV];  // [half][row][dim]
__device__ float    g_pm[2 * BS];
__device__ float    g_pl[2 * BS];

// ---------------------------------------------------------------------------
// helpers
// ---------------------------------------------------------------------------
__device__ __forceinline__ float f2tff(float f) {
    unsigned u;
    asm("cvt.rna.tf32.f32 %0, %1;" : "=r"(u) : "f"(f));
    return __uint_as_float(u);
}
// D(16x8,f32) += A(16x8,tf32,row) * B(8x8,tf32,col)
__device__ __forceinline__ void mma8(float* c, unsigned a0, unsigned a1,
                                     unsigned a2, unsigned a3,
                                     unsigned b0, unsigned b1) {
    asm volatile(
        "mma.sync.aligned.m16n8k8.row.col.f32.tf32.tf32.f32 "
        "{%0,%1,%2,%3}, {%4,%5,%6,%7}, {%8,%9}, {%0,%1,%2,%3};\n"
        : "+f"(c[0]), "+f"(c[1]), "+f"(c[2]), "+f"(c[3])
        : "r"(a0), "r"(a1), "r"(a2), "r"(a3), "r"(b0), "r"(b1));
}
// D(16x8,f32) += A(16x16,f16,row) * B(16x8,f16,col)
__device__ __forceinline__ void mma16(float* c, unsigned a0, unsigned a1,
                                      unsigned a2, unsigned a3,
                                      unsigned b0, unsigned b1) {
    asm volatile(
        "mma.sync.aligned.m16n8k16.row.col.f32.f16.f16.f32 "
        "{%0,%1,%2,%3}, {%4,%5,%6,%7}, {%8,%9}, {%0,%1,%2,%3};\n"
        : "+f"(c[0]), "+f"(c[1]), "+f"(c[2]), "+f"(c[3])
        : "r"(a0), "r"(a1), "r"(a2), "r"(a3), "r"(b0), "r"(b1));
}
__device__ __forceinline__ unsigned packh2(float hi, float lo) {
    unsigned d;
    asm("cvt.rn.f16x2.f32 %0, %1, %2;" : "=r"(d) : "f"(hi), "f"(lo));
    return d;
}
__device__ __forceinline__ unsigned ex2h2(unsigned x) {
    unsigned d;
    asm("ex2.approx.f16x2 %0, %1;" : "=r"(d) : "r"(x));
    return d;
}
__device__ __forceinline__ void cpa16(uint32_t saddr, const void* gaddr) {
    asm volatile("cp.async.cg.shared.global [%0], [%1], 16;\n"
                 :: "r"(saddr), "l"(gaddr));
}
__device__ __forceinline__ void cpa_commit() {
    asm volatile("cp.async.commit_group;\n");
}
__device__ __forceinline__ void cpa_wait0() {
    asm volatile("cp.async.wait_group 0;\n");
}
__device__ __forceinline__ void cpa_wait1() {
    asm volatile("cp.async.wait_group 1;\n");
}

// ---------------------------------------------------------------------------
// Kernel 1: fold Wo over identical heads -> half, transposed [n][k]
// ---------------------------------------------------------------------------
__global__ void woeff_kernel(const float* __restrict__ Wo) {
    int idx = blockIdx.x * blockDim.x + threadIdx.x;   // 64*512
    if (idx < DV * DD) {
        int r = idx >> 9;          // k (0..63)
        int c = idx & 511;         // n (0..511)
        float s = 0.f;
#pragma unroll
        for (int h = 0; h < HH; ++h) s += Wo[((h << 6) + r) * DD + c];
        ((__half*)g_woT2)[c * 64 + r] = __float2half(s);
    }
}

// ---------------------------------------------------------------------------
// Kernel 2: fused projections on tf32 tensor cores; epilogue emits fp16.
// blockIdx.y: 0 -> q (scaled 0.125); 1 -> k AND vT (shared A tile).
// ---------------------------------------------------------------------------
__global__ void __launch_bounds__(128) proj_mma_kernel(
    const float* __restrict__ query, const float* __restrict__ key,
    const float* __restrict__ Wq, const float* __restrict__ bq,
    const float* __restrict__ Wk, const float* __restrict__ bk,
    const float* __restrict__ Wv, const float* __restrict__ bv)
{
    const int fused = blockIdx.y;           // 0: q, 1: k+v
    const float* A  = fused ? key : query;
    const int m0 = blockIdx.x * 64;

    __shared__ float As[64][36];
    __shared__ float W1s[32][72];
    __shared__ float W2s[32][72];

    const int t    = threadIdx.x;
    const int w    = t >> 5;
    const int lane = t & 31;
    const int g    = lane >> 2;
    const int t4   = lane & 3;

    float c1[8][4] = {};
    float c2[8][4] = {};

    for (int kk = 0; kk < DD; kk += 32) {
        __syncthreads();
#pragma unroll
        for (int u = 0; u < 4; ++u) {
            int fi = t + u * 128;
            int r  = fi >> 3;
            int c4 = (fi & 7) << 2;
            float4 a4 = *(const float4*)(A + (size_t)(m0 + r) * DD + kk + c4);
            As[r][c4 + 0] = f2tff(a4.x);
            As[r][c4 + 1] = f2tff(a4.y);
            As[r][c4 + 2] = f2tff(a4.z);
            As[r][c4 + 3] = f2tff(a4.w);
        }
#pragma unroll
        for (int u = 0; u < 4; ++u) {
            int fi = t + u * 128;
            int r  = fi >> 4;
            int c4 = (fi & 15) << 2;
            const float* Wa = fused ? Wk : Wq;
            float4 w4 = *(const float4*)(Wa + (size_t)(kk + r) * DK + c4);
            W1s[r][c4 + 0] = f2tff(w4.x);
            W1s[r][c4 + 1] = f2tff(w4.y);
            W1s[r][c4 + 2] = f2tff(w4.z);
            W1s[r][c4 + 3] = f2tff(w4.w);
            if (fused) {
                float4 v4 = *(const float4*)(Wv + (size_t)(kk + r) * DK + c4);
                W2s[r][c4 + 0] = f2tff(v4.x);
                W2s[r][c4 + 1] = f2tff(v4.y);
                W2s[r][c4 + 2] = f2tff(v4.z);
                W2s[r][c4 + 3] = f2tff(v4.w);
            }
        }
        __syncthreads();

#pragma unroll
        for (int kt = 0; kt < 4; ++kt) {
            unsigned a0 = __float_as_uint(As[w * 16 + g    ][kt * 8 + t4    ]);
            unsigned a1 = __float_as_uint(As[w * 16 + g + 8][kt * 8 + t4    ]);
            unsigned a2 = __float_as_uint(As[w * 16 + g    ][kt * 8 + t4 + 4]);
            unsigned a3 = __float_as_uint(As[w * 16 + g + 8][kt * 8 + t4 + 4]);
#pragma unroll
            for (int nt = 0; nt < 8; ++nt) {
                unsigned b0 = __float_as_uint(W1s[kt * 8 + t4    ][nt * 8 + g]);
                unsigned b1 = __float_as_uint(W1s[kt * 8 + t4 + 4][nt * 8 + g]);
                mma8(c1[nt], a0, a1, a2, a3, b0, b1);
            }
            if (fused) {
#pragma unroll
                for (int nt = 0; nt < 8; ++nt) {
                    unsigned b0 = __float_as_uint(W2s[kt * 8 + t4    ][nt * 8 + g]);
                    unsigned b1 = __float_as_uint(W2s[kt * 8 + t4 + 4][nt * 8 + g]);
                    mma8(c2[nt], a0, a1, a2, a3, b0, b1);
                }
            }
        }
    }

    // epilogue -> fp16
    const int r0 = m0 + w * 16 + g;            // global row
    const float* bias1 = fused ? bk : bq;
    unsigned* out1     = fused ? g_k2 : g_q2;
    const float sc     = fused ? 1.0f : 0.125f;
#pragma unroll
    for (int nt = 0; nt < 8; ++nt) {
        int cc = nt * 8 + 2 * t4;
        float b0 = bias1[cc], b1 = bias1[cc + 1];
        out1[r0 * 32 + (cc >> 1)] =
            packh2((c1[nt][1] + b1) * sc, (c1[nt][0] + b0) * sc);
        out1[(r0 + 8) * 32 + (cc >> 1)] =
            packh2((c1[nt][3] + b1) * sc, (c1[nt][2] + b0) * sc);
    }
    if (fused) {
        const int bq_ = r0 >> 11;              // batch
        const int sq  = r0 & 2047;             // seq within batch
#pragma unroll
        for (int nt = 0; nt < 8; ++nt) {
            int cc = nt * 8 + 2 * t4;
            float b0 = bv[cc], b1 = bv[cc + 1];
            __half* base0 = g_vT + ((size_t)bq_ * 64 + cc) * SS;
            __half* base1 = g_vT + ((size_t)bq_ * 64 + cc + 1) * SS;
            base0[sq]     = __float2half(c2[nt][0] + b0);
            base1[sq]     = __float2half(c2[nt][1] + b1);
            base0[sq + 8] = __float2half(c2[nt][2] + b0);
            base1[sq + 8] = __float2half(c2[nt][3] + b1);
        }
    }
}

// ---------------------------------------------------------------------------
// Kernel 3: causal flash attention, fp16, SPLIT-KV (2 halves per q-tile).
// Block = 64 q-rows x half the KV range; 128 threads = 4 warps.
// blockIdx.x: b = &3 ; rest>>1 -> q-tile (longest first) ; rest&1 -> kv half.
// Emits unnormalized fp32 partials (acc, m, l).
// ---------------------------------------------------------------------------
#define P32 36
__global__ void __launch_bounds__(128) attn_kernel() {
    __shared__ unsigned kb[2][64 * P32];
    __shared__ unsigned vb[2][64 * P32];

    const int b    = blockIdx.x & 3;
    const int rest = blockIdx.x >> 2;
    const int it   = (NQT2 - 1) - (rest >> 1);   // longest-first
    const int h    = rest & 1;
    const int n    = it + 1;                     // total KV tiles for this q-tile
    const int jt0  = h ? (n + 1) / 2 : 0;
    const int jt1  = h ? n : (n + 1) / 2;

    const int t    = threadIdx.x;
    const int w    = t >> 5;
    const int lane = t & 31;
    const int g    = lane >> 2;
    const int t4   = lane & 3;
    const int r0   = w * 16 + g;
    const unsigned FULL = 0xffffffffu;
    const unsigned ONES2 = 0x3C003C00u;
    const float L2E = 1.44269504f;

    const size_t rowbase = (size_t)(b * SS + it * QT2);

    if (jt0 >= jt1) {
        // empty half: neutral partials
        float4 z = make_float4(0.f, 0.f, 0.f, 0.f);
        float* pa = g_pacc + ((size_t)h * BS + rowbase) * DV;
#pragma unroll
        for (int u = 0; u < 8; ++u) ((float4*)pa)[t + u * 128] = z;
        if (t < 64) {
            g_pm[h * BS + rowbase + t] = -1e30f;
            g_pl[h * BS + rowbase + t] = 0.f;
        }
        return;
    }

    // ---- Q A-fragments straight from gmem ----
    const unsigned* qg = g_q2 + rowbase * 32;
    unsigned aq[4][4];
#pragma unroll
    for (int kt = 0; kt < 4; ++kt) {
        aq[kt][0] = qg[(r0    ) * 32 + kt * 8 + t4    ];
        aq[kt][1] = qg[(r0 + 8) * 32 + kt * 8 + t4    ];
        aq[kt][2] = qg[(r0    ) * 32 + kt * 8 + t4 + 4];
        aq[kt][3] = qg[(r0 + 8) * 32 + kt * 8 + t4 + 4];
    }

    const __half* kgp = (const __half*)g_k2 + (size_t)(b * SS) * DK;
    const __half* vgp = g_vT + (size_t)b * 64 * SS;
    const int qpos0 = it * QT2 + r0;

    // prologue: tile jt0 -> buffer 0 (4 K-chunks + 4 V-chunks per thread)
    {
        uint32_t kba = (uint32_t)__cvta_generic_to_shared(&kb[0][0]);
        uint32_t vba = (uint32_t)__cvta_generic_to_shared(&vb[0][0]);
        const __half* kg0 = kgp + (size_t)jt0 * 64 * DK;
        const __half* vg0 = vgp + (size_t)jt0 * 64;
#pragma unroll
        for (int u = 0; u < 4; ++u) {
            int fi = t + u * 128;
            int r  = fi >> 3;
            int c  = fi & 7;
            cpa16(kba + (r * P32 + c * 4) * 4, kg0 + (size_t)r * DK + c * 8);
            cpa16(vba + (r * P32 + c * 4) * 4, vg0 + (size_t)r * SS + c * 8);
        }
        cpa_commit();
    }

    float o[8][4] = {};
    float mrow0 = -1e30f, mrow1 = -1e30f;
    float lrow0 = 0.f,    lrow1 = 0.f;

    for (int jt = jt0; jt < jt1; ++jt) {
        const int cur = (jt - jt0) & 1;
        if (jt > jt0) __syncthreads();
        if (jt + 1 < jt1) {
            const int nxt = cur ^ 1;
            uint32_t kba = (uint32_t)__cvta_generic_to_shared(&kb[nxt][0]);
            uint32_t vba = (uint32_t)__cvta_generic_to_shared(&vb[nxt][0]);
            const __half* kgn = kgp + (size_t)(jt + 1) * 64 * DK;
            const __half* vgn = vgp + (size_t)(jt + 1) * 64;
#pragma unroll
            for (int u = 0; u < 4; ++u) {
                int fi = t + u * 128;
                int r  = fi >> 3;
                int c  = fi & 7;
                cpa16(kba + (r * P32 + c * 4) * 4, kgn + (size_t)r * DK + c * 8);
                cpa16(vba + (r * P32 + c * 4) * 4, vgn + (size_t)r * SS + c * 8);
            }
            cpa_commit();
            cpa_wait1();
        } else {
            cpa_wait0();
        }
        __syncthreads();

        const unsigned* kc = &kb[cur][0];
        const unsigned* vc = &vb[cur][0];

        // ---- S = Q K^T ----
        float c[8][4] = {};
#pragma unroll
        for (int kt = 0; kt < 4; ++kt) {
#pragma unroll
            for (int nt = 0; nt < 8; ++nt) {
                unsigned b0 = kc[(nt * 8 + g) * P32 + kt * 8 + t4    ];
                unsigned b1 = kc[(nt * 8 + g) * P32 + kt * 8 + t4 + 4];
                mma16(c[nt], aq[kt][0], aq[kt][1], aq[kt][2], aq[kt][3], b0, b1);
            }
        }

        // ---- causal mask (true diagonal tile only) ----
        if (jt == n - 1) {
#pragma unroll
            for (int nt = 0; nt < 8; ++nt) {
                int kp = jt * 64 + nt * 8 + 2 * t4;
                if (kp     > qpos0)     c[nt][0] = -1e30f;
                if (kp + 1 > qpos0)     c[nt][1] = -1e30f;
                if (kp     > qpos0 + 8) c[nt][2] = -1e30f;
                if (kp + 1 > qpos0 + 8) c[nt][3] = -1e30f;
            }
        }

        // ---- warp-local online softmax ----
        float rm0 = -1e30f, rm1 = -1e30f;
#pragma unroll
        for (int nt = 0; nt < 8; ++nt) {
            rm0 = fmaxf(rm0, fmaxf(c[nt][0], c[nt][1]));
            rm1 = fmaxf(rm1, fmaxf(c[nt][2], c[nt][3]));
        }
        rm0 = fmaxf(rm0, __shfl_xor_sync(FULL, rm0, 1));
        rm0 = fmaxf(rm0, __shfl_xor_sync(FULL, rm0, 2));
        rm1 = fmaxf(rm1, __shfl_xor_sync(FULL, rm1, 1));
        rm1 = fmaxf(rm1, __shfl_xor_sync(FULL, rm1, 2));

        float nm0 = fmaxf(mrow0, rm0);
        float nm1 = fmaxf(mrow1, rm1);
        float corr0 = __expf(mrow0 - nm0); mrow0 = nm0;
        float corr1 = __expf(mrow1 - nm1); mrow1 = nm1;
        float nl0 = nm0 * L2E;
        float nl1 = nm1 * L2E;

#pragma unroll
        for (int nt = 0; nt < 8; ++nt) {
            o[nt][0] *= corr0; o[nt][1] *= corr0;
            o[nt][2] *= corr1; o[nt][3] *= corr1;
        }

        // ---- exp -> PV A-frags + ones-MMA row sums + PV MMA ----
        float ds[4] = {0.f, 0.f, 0.f, 0.f};
#pragma unroll
        for (int kt = 0; kt < 4; ++kt) {
            int ne = 2 * kt, no_ = 2 * kt + 1;
            unsigned aP0 = ex2h2(packh2(c[ne ][1] * L2E - nl0, c[ne ][0] * L2E - nl0));
            unsigned aP1 = ex2h2(packh2(c[ne ][3] * L2E - nl1, c[ne ][2] * L2E - nl1));
            unsigned aP2 = ex2h2(packh2(c[no_][1] * L2E - nl0, c[no_][0] * L2E - nl0));
            unsigned aP3 = ex2h2(packh2(c[no_][3] * L2E - nl1, c[no_][2] * L2E - nl1));
            mma16(ds, aP0, aP1, aP2, aP3, ONES2, ONES2);
#pragma unroll
            for (int nt = 0; nt < 8; ++nt) {
                unsigned b0 = vc[(nt * 8 + g) * P32 + kt * 8 + t4    ];
                unsigned b1 = vc[(nt * 8 + g) * P32 + kt * 8 + t4 + 4];
                mma16(o[nt], aP0, aP1, aP2, aP3, b0, b1);
            }
        }
        lrow0 = lrow0 * corr0 + ds[0];
        lrow1 = lrow1 * corr1 + ds[2];
    }

    // ---- epilogue: unnormalized fp32 partials ----
    float* pa = g_pacc + ((size_t)h * BS + rowbase) * DV;
#pragma unroll
    for (int nt = 0; nt < 8; ++nt) {
        int dc = nt * 8 + 2 * t4;
        *(float2*)(pa + (size_t)r0 * DV + dc)       = make_float2(o[nt][0], o[nt][1]);
        *(float2*)(pa + (size_t)(r0 + 8) * DV + dc) = make_float2(o[nt][2], o[nt][3]);
    }
    if (t4 == 0) {
        g_pm[h * BS + rowbase + r0]     = mrow0;
        g_pl[h * BS + rowbase + r0]     = lrow0;
        g_pm[h * BS + rowbase + r0 + 8] = mrow1;
        g_pl[h * BS + rowbase + r0 + 8] = lrow1;
    }
}

// ---------------------------------------------------------------------------
// Kernel 3b: merge the two KV halves -> half2 g_o2
// ---------------------------------------------------------------------------
__global__ void __launch_bounds__(256) merge_kernel() {
    int tid = blockIdx.x * blockDim.x + threadIdx.x;  // BS*32
    int row = tid >> 5;
    int d2  = tid & 31;
    float m0 = g_pm[row],      m1 = g_pm[BS + row];
    float l0 = g_pl[row],      l1 = g_pl[BS + row];
    float M  = fmaxf(m0, m1);
    float s0 = __expf(m0 - M);
    float s1 = __expf(m1 - M);
    float inv = 1.f / (l0 * s0 + l1 * s1);
    float2 a0 = *(const float2*)(g_pacc + (size_t)row * DV + 2 * d2);
    float2 a1 = *(const float2*)(g_pacc + (size_t)(BS + row) * DV + 2 * d2);
    g_o2[row * 32 + d2] = packh2((a0.y * s0 + a1.y * s1) * inv,
                                 (a0.x * s0 + a1.x * s1) * inv);
}

// ---------------------------------------------------------------------------
// Kernel 4: out[8192,512] = o[8192,64] @ woeff[64,512] + bo  (fp16 mma)
// 256 threads = 8 warps; block = 64 rows x 128 cols; K = 64 single shot.
// ---------------------------------------------------------------------------
__global__ void __launch_bounds__(256) outgemm_mma_kernel(
    const float* __restrict__ bo, float* __restrict__ out)
{
    const int m0 = blockIdx.x * 64;
    const int n0 = blockIdx.y * 128;

    __shared__ unsigned Ao[64 * P32];     // o tile [row][k-half2], pitch 36
    __shared__ unsigned Ws[128 * P32];    // woT tile [n][k-half2], pitch 36

    const int t    = threadIdx.x;
    const int w    = t >> 5;
    const int lane = t & 31;
    const int g    = lane >> 2;
    const int t4   = lane & 3;
    const int rw   = (w & 3) * 16;
    const int cw   = (w >> 2) * 64;

#pragma unroll
    for (int u = 0; u < 2; ++u) {
        int fi = t + u * 256;
        int r  = fi >> 3;
        int c  = (fi & 7) << 2;
        *(float4*)&Ao[r * P32 + c] = *(const float4*)(g_o2 + (size_t)(m0 + r) * 32 + c);
    }
#pragma unroll
    for (int u = 0; u < 4; ++u) {
        int fi = t + u * 256;
        int r  = fi >> 3;
        int c  = (fi & 7) << 2;
        *(float4*)&Ws[r * P32 + c] = *(const float4*)(g_woT2 + (size_t)(n0 + r) * 32 + c);
    }
    __syncthreads();

    float acc[8][4] = {};
#pragma unroll
    for (int kt = 0; kt < 4; ++kt) {
        unsigned a0 = Ao[(rw + g    ) * P32 + kt * 8 + t4    ];
        unsigned a1 = Ao[(rw + g + 8) * P32 + kt * 8 + t4    ];
        unsigned a2 = Ao[(rw + g    ) * P32 + kt * 8 + t4 + 4];
        unsigned a3 = Ao[(rw + g + 8) * P32 + kt * 8 + t4 + 4];
#pragma unroll
        for (int nt = 0; nt < 8; ++nt) {
            unsigned b0 = Ws[(cw + nt * 8 + g) * P32 + kt * 8 + t4    ];
            unsigned b1 = Ws[(cw + nt * 8 + g) * P32 + kt * 8 + t4 + 4];
            mma16(acc[nt], a0, a1, a2, a3, b0, b1);
        }
    }

    const int row0 = m0 + rw + g;
#pragma unroll
    for (int nt = 0; nt < 8; ++nt) {
        int cc = n0 + cw + nt * 8 + 2 * t4;
        float b0 = bo[cc], b1 = bo[cc + 1];
        *(float2*)(out + (size_t)row0 * DD + cc)       = make_float2(acc[nt][0] + b0, acc[nt][1] + b1);
        *(float2*)(out + (size_t)(row0 + 8) * DD + cc) = make_float2(acc[nt][2] + b0, acc[nt][3] + b1);
    }
}

// ---------------------------------------------------------------------------
// Launch
// Inputs: 0 query, 1 key, 2 value(unused), 3 Wq, 4 bq, 5 Wk, 6 bk,
//         7 Wv, 8 bv, 9 Wo, 10 bo
// ---------------------------------------------------------------------------
extern "C" void kernel_launch(void* const* d_in, const int* in_sizes, int n_in,
                              void* d_out, int out_size)
{
    const float* query = (const float*)d_in[0];
    const float* key   = (const float*)d_in[1];
    const float* Wq    = (const float*)d_in[3];
    const float* bq    = (const float*)d_in[4];
    const float* Wk    = (const float*)d_in[5];
    const float* bk    = (const float*)d_in[6];
    const float* Wv    = (const float*)d_in[7];
    const float* bv    = (const float*)d_in[8];
    const float* Wo    = (const float*)d_in[9];
    const float* bo    = (const float*)d_in[10];
    float* out = (float*)d_out;

    woeff_kernel<<<64, 512>>>(Wo);
    proj_mma_kernel<<<dim3(BS / 64, 2), 128>>>(query, key, Wq, bq, Wk, bk, Wv, bv);
    attn_kernel<<<BB * NQT2 * 2, 128>>>();
    merge_kernel<<<BS * 32 / 256, 256>>>();
    outgemm_mma_kernel<<<dim3(BS / 64, DD / 128), 256>>>(bo, out);
}

// round 10
// speedup vs baseline: 1.3772x; 1.0439x over previous
#include <cuda_runtime.h>
#include <cuda_fp16.h>
#include <cstdint>

// Problem constants
#define BB 4
#define SS 2048
#define DD 512
#define HH 8
#define DK 64
#define DV 64
#define BS (BB * SS)          // 8192 rows total
#define QT2 64                // query rows per attention block
#define NQT2 (SS / QT2)       // 32 q-tiles per batch
#define NSPL 4                // KV splits per q-tile

// Scratch (device globals: no allocations allowed)
__device__ unsigned g_q2[BS * DK / 2];    // half2: (q@Wq+bq)*0.125, [row][32 u32]
__device__ unsigned g_k2[BS * DK / 2];    // half2: k, [row][32 u32]
__device__ __half   g_vT[BB * DV * SS];   // half, per-batch transposed [dim][seq]
__device__ unsigned g_o2[BS * DV / 2];    // half2: merged attention out
__device__ unsigned g_woT2[DD * DV / 2];  // half2: woeff^T [n][k], [512][32 u32]
// split-KV partials (fp32, unnormalized)
__device__ float    g_pacc[NSPL * BS * DV];  // [split][row][dim]
__device__ float    g_pm[NSPL * BS];
__device__ float    g_pl[NSPL * BS];

// ---------------------------------------------------------------------------
// helpers
// ---------------------------------------------------------------------------
__device__ __forceinline__ float f2tff(float f) {
    unsigned u;
    asm("cvt.rna.tf32.f32 %0, %1;" : "=r"(u) : "f"(f));
    return __uint_as_float(u);
}
// D(16x8,f32) += A(16x8,tf32,row) * B(8x8,tf32,col)
__device__ __forceinline__ void mma8(float* c, unsigned a0, unsigned a1,
                                     unsigned a2, unsigned a3,
                                     unsigned b0, unsigned b1) {
    asm volatile(
        "mma.sync.aligned.m16n8k8.row.col.f32.tf32.tf32.f32 "
        "{%0,%1,%2,%3}, {%4,%5,%6,%7}, {%8,%9}, {%0,%1,%2,%3};\n"
        : "+f"(c[0]), "+f"(c[1]), "+f"(c[2]), "+f"(c[3])
        : "r"(a0), "r"(a1), "r"(a2), "r"(a3), "r"(b0), "r"(b1));
}
// D(16x8,f32) += A(16x16,f16,row) * B(16x8,f16,col)
__device__ __forceinline__ void mma16(float* c, unsigned a0, unsigned a1,
                                      unsigned a2, unsigned a3,
                                      unsigned b0, unsigned b1) {
    asm volatile(
        "mma.sync.aligned.m16n8k16.row.col.f32.f16.f16.f32 "
        "{%0,%1,%2,%3}, {%4,%5,%6,%7}, {%8,%9}, {%0,%1,%2,%3};\n"
        : "+f"(c[0]), "+f"(c[1]), "+f"(c[2]), "+f"(c[3])
        : "r"(a0), "r"(a1), "r"(a2), "r"(a3), "r"(b0), "r"(b1));
}
__device__ __forceinline__ unsigned packh2(float hi, float lo) {
    unsigned d;
    asm("cvt.rn.f16x2.f32 %0, %1, %2;" : "=r"(d) : "f"(hi), "f"(lo));
    return d;
}
__device__ __forceinline__ unsigned ex2h2(unsigned x) {
    unsigned d;
    asm("ex2.approx.f16x2 %0, %1;" : "=r"(d) : "r"(x));
    return d;
}
__device__ __forceinline__ void cpa16(uint32_t saddr, const void* gaddr) {
    asm volatile("cp.async.cg.shared.global [%0], [%1], 16;\n"
                 :: "r"(saddr), "l"(gaddr));
}
__device__ __forceinline__ void cpa_commit() {
    asm volatile("cp.async.commit_group;\n");
}
__device__ __forceinline__ void cpa_wait0() {
    asm volatile("cp.async.wait_group 0;\n");
}
__device__ __forceinline__ void cpa_wait1() {
    asm volatile("cp.async.wait_group 1;\n");
}

// ---------------------------------------------------------------------------
// Kernel 1: fold Wo over identical heads -> half, transposed [n][k]
// ---------------------------------------------------------------------------
__global__ void woeff_kernel(const float* __restrict__ Wo) {
    int idx = blockIdx.x * blockDim.x + threadIdx.x;   // 64*512
    if (idx < DV * DD) {
        int r = idx >> 9;          // k (0..63)
        int c = idx & 511;         // n (0..511)
        float s = 0.f;
#pragma unroll
        for (int h = 0; h < HH; ++h) s += Wo[((h << 6) + r) * DD + c];
        ((__half*)g_woT2)[c * 64 + r] = __float2half(s);
    }
}

// ---------------------------------------------------------------------------
// Kernel 2: fused projections on tf32 tensor cores; epilogue emits fp16.
// blockIdx.y: 0 -> q (scaled 0.125); 1 -> k AND vT (shared A tile).
// ---------------------------------------------------------------------------
__global__ void __launch_bounds__(128) proj_mma_kernel(
    const float* __restrict__ query, const float* __restrict__ key,
    const float* __restrict__ Wq, const float* __restrict__ bq,
    const float* __restrict__ Wk, const float* __restrict__ bk,
    const float* __restrict__ Wv, const float* __restrict__ bv)
{
    const int fused = blockIdx.y;           // 0: q, 1: k+v
    const float* A  = fused ? key : query;
    const int m0 = blockIdx.x * 64;

    __shared__ float As[64][36];
    __shared__ float W1s[32][72];
    __shared__ float W2s[32][72];

    const int t    = threadIdx.x;
    const int w    = t >> 5;
    const int lane = t & 31;
    const int g    = lane >> 2;
    const int t4   = lane & 3;

    float c1[8][4] = {};
    float c2[8][4] = {};

    for (int kk = 0; kk < DD; kk += 32) {
        __syncthreads();
#pragma unroll
        for (int u = 0; u < 4; ++u) {
            int fi = t + u * 128;
            int r  = fi >> 3;
            int c4 = (fi & 7) << 2;
            float4 a4 = *(const float4*)(A + (size_t)(m0 + r) * DD + kk + c4);
            As[r][c4 + 0] = f2tff(a4.x);
            As[r][c4 + 1] = f2tff(a4.y);
            As[r][c4 + 2] = f2tff(a4.z);
            As[r][c4 + 3] = f2tff(a4.w);
        }
#pragma unroll
        for (int u = 0; u < 4; ++u) {
            int fi = t + u * 128;
            int r  = fi >> 4;
            int c4 = (fi & 15) << 2;
            const float* Wa = fused ? Wk : Wq;
            float4 w4 = *(const float4*)(Wa + (size_t)(kk + r) * DK + c4);
            W1s[r][c4 + 0] = f2tff(w4.x);
            W1s[r][c4 + 1] = f2tff(w4.y);
            W1s[r][c4 + 2] = f2tff(w4.z);
            W1s[r][c4 + 3] = f2tff(w4.w);
            if (fused) {
                float4 v4 = *(const float4*)(Wv + (size_t)(kk + r) * DK + c4);
                W2s[r][c4 + 0] = f2tff(v4.x);
                W2s[r][c4 + 1] = f2tff(v4.y);
                W2s[r][c4 + 2] = f2tff(v4.z);
                W2s[r][c4 + 3] = f2tff(v4.w);
            }
        }
        __syncthreads();

#pragma unroll
        for (int kt = 0; kt < 4; ++kt) {
            unsigned a0 = __float_as_uint(As[w * 16 + g    ][kt * 8 + t4    ]);
            unsigned a1 = __float_as_uint(As[w * 16 + g + 8][kt * 8 + t4    ]);
            unsigned a2 = __float_as_uint(As[w * 16 + g    ][kt * 8 + t4 + 4]);
            unsigned a3 = __float_as_uint(As[w * 16 + g + 8][kt * 8 + t4 + 4]);
#pragma unroll
            for (int nt = 0; nt < 8; ++nt) {
                unsigned b0 = __float_as_uint(W1s[kt * 8 + t4    ][nt * 8 + g]);
                unsigned b1 = __float_as_uint(W1s[kt * 8 + t4 + 4][nt * 8 + g]);
                mma8(c1[nt], a0, a1, a2, a3, b0, b1);
            }
            if (fused) {
#pragma unroll
                for (int nt = 0; nt < 8; ++nt) {
                    unsigned b0 = __float_as_uint(W2s[kt * 8 + t4    ][nt * 8 + g]);
                    unsigned b1 = __float_as_uint(W2s[kt * 8 + t4 + 4][nt * 8 + g]);
                    mma8(c2[nt], a0, a1, a2, a3, b0, b1);
                }
            }
        }
    }

    // epilogue -> fp16
    const int r0 = m0 + w * 16 + g;            // global row
    const float* bias1 = fused ? bk : bq;
    unsigned* out1     = fused ? g_k2 : g_q2;
    const float sc     = fused ? 1.0f : 0.125f;
#pragma unroll
    for (int nt = 0; nt < 8; ++nt) {
        int cc = nt * 8 + 2 * t4;
        float b0 = bias1[cc], b1 = bias1[cc + 1];
        out1[r0 * 32 + (cc >> 1)] =
            packh2((c1[nt][1] + b1) * sc, (c1[nt][0] + b0) * sc);
        out1[(r0 + 8) * 32 + (cc >> 1)] =
            packh2((c1[nt][3] + b1) * sc, (c1[nt][2] + b0) * sc);
    }
    if (fused) {
        const int bq_ = r0 >> 11;              // batch
        const int sq  = r0 & 2047;             // seq within batch
#pragma unroll
        for (int nt = 0; nt < 8; ++nt) {
            int cc = nt * 8 + 2 * t4;
            float b0 = bv[cc], b1 = bv[cc + 1];
            __half* base0 = g_vT + ((size_t)bq_ * 64 + cc) * SS;
            __half* base1 = g_vT + ((size_t)bq_ * 64 + cc + 1) * SS;
            base0[sq]     = __float2half(c2[nt][0] + b0);
            base1[sq]     = __float2half(c2[nt][1] + b1);
            base0[sq + 8] = __float2half(c2[nt][2] + b0);
            base1[sq + 8] = __float2half(c2[nt][3] + b1);
        }
    }
}

// ---------------------------------------------------------------------------
// Kernel 3: causal flash attention, fp16, SPLIT-KV (4 splits per q-tile).
// Block = 64 q-rows x quarter of the KV range; 128 threads = 4 warps.
// blockIdx.x: b = &3 ; rest>>2 -> q-tile (longest first) ; rest&3 -> split.
// Emits unnormalized fp32 partials (acc, m, l).
// ---------------------------------------------------------------------------
#define P32 36
__global__ void __launch_bounds__(128) attn_kernel() {
    __shared__ unsigned kb[2][64 * P32];
    __shared__ unsigned vb[2][64 * P32];

    const int b    = blockIdx.x & 3;
    const int rest = blockIdx.x >> 2;
    const int it   = (NQT2 - 1) - (rest >> 2);   // longest-first
    const int s    = rest & 3;
    const int n    = it + 1;                     // total KV tiles for this q-tile
    const int jt0  = (s * n) / NSPL;
    const int jt1  = ((s + 1) * n) / NSPL;

    const int t    = threadIdx.x;
    const int w    = t >> 5;
    const int lane = t & 31;
    const int g    = lane >> 2;
    const int t4   = lane & 3;
    const int r0   = w * 16 + g;
    const unsigned FULL = 0xffffffffu;
    const unsigned ONES2 = 0x3C003C00u;
    const float L2E = 1.44269504f;

    const size_t rowbase = (size_t)(b * SS + it * QT2);

    if (jt0 >= jt1) {
        // empty split: neutral partials
        float4 z = make_float4(0.f, 0.f, 0.f, 0.f);
        float* pa = g_pacc + ((size_t)s * BS + rowbase) * DV;
#pragma unroll
        for (int u = 0; u < 8; ++u) ((float4*)pa)[t + u * 128] = z;
        if (t < 64) {
            g_pm[s * BS + rowbase + t] = -1e30f;
            g_pl[s * BS + rowbase + t] = 0.f;
        }
        return;
    }

    // ---- Q A-fragments straight from gmem ----
    const unsigned* qg = g_q2 + rowbase * 32;
    unsigned aq[4][4];
#pragma unroll
    for (int kt = 0; kt < 4; ++kt) {
        aq[kt][0] = qg[(r0    ) * 32 + kt * 8 + t4    ];
        aq[kt][1] = qg[(r0 + 8) * 32 + kt * 8 + t4    ];
        aq[kt][2] = qg[(r0    ) * 32 + kt * 8 + t4 + 4];
        aq[kt][3] = qg[(r0 + 8) * 32 + kt * 8 + t4 + 4];
    }

    const __half* kgp = (const __half*)g_k2 + (size_t)(b * SS) * DK;
    const __half* vgp = g_vT + (size_t)b * 64 * SS;
    const int qpos0 = it * QT2 + r0;

    // prologue: tile jt0 -> buffer 0 (4 K-chunks + 4 V-chunks per thread)
    {
        uint32_t kba = (uint32_t)__cvta_generic_to_shared(&kb[0][0]);
        uint32_t vba = (uint32_t)__cvta_generic_to_shared(&vb[0][0]);
        const __half* kg0 = kgp + (size_t)jt0 * 64 * DK;
        const __half* vg0 = vgp + (size_t)jt0 * 64;
#pragma unroll
        for (int u = 0; u < 4; ++u) {
            int fi = t + u * 128;
            int r  = fi >> 3;
            int c  = fi & 7;
            cpa16(kba + (r * P32 + c * 4) * 4, kg0 + (size_t)r * DK + c * 8);
            cpa16(vba + (r * P32 + c * 4) * 4, vg0 + (size_t)r * SS + c * 8);
        }
        cpa_commit();
    }

    float o[8][4] = {};
    float mrow0 = -1e30f, mrow1 = -1e30f;
    float lrow0 = 0.f,    lrow1 = 0.f;

    for (int jt = jt0; jt < jt1; ++jt) {
        const int cur = (jt - jt0) & 1;
        if (jt > jt0) __syncthreads();
        if (jt + 1 < jt1) {
            const int nxt = cur ^ 1;
            uint32_t kba = (uint32_t)__cvta_generic_to_shared(&kb[nxt][0]);
            uint32_t vba = (uint32_t)__cvta_generic_to_shared(&vb[nxt][0]);
            const __half* kgn = kgp + (size_t)(jt + 1) * 64 * DK;
            const __half* vgn = vgp + (size_t)(jt + 1) * 64;
#pragma unroll
            for (int u = 0; u < 4; ++u) {
                int fi = t + u * 128;
                int r  = fi >> 3;
                int c  = fi & 7;
                cpa16(kba + (r * P32 + c * 4) * 4, kgn + (size_t)r * DK + c * 8);
                cpa16(vba + (r * P32 + c * 4) * 4, vgn + (size_t)r * SS + c * 8);
            }
            cpa_commit();
            cpa_wait1();
        } else {
            cpa_wait0();
        }
        __syncthreads();

        const unsigned* kc = &kb[cur][0];
        const unsigned* vc = &vb[cur][0];

        // ---- S = Q K^T ----
        float c[8][4] = {};
#pragma unroll
        for (int kt = 0; kt < 4; ++kt) {
#pragma unroll
            for (int nt = 0; nt < 8; ++nt) {
                unsigned b0 = kc[(nt * 8 + g) * P32 + kt * 8 + t4    ];
                unsigned b1 = kc[(nt * 8 + g) * P32 + kt * 8 + t4 + 4];
                mma16(c[nt], aq[kt][0], aq[kt][1], aq[kt][2], aq[kt][3], b0, b1);
            }
        }

        // ---- causal mask (true diagonal tile only) ----
        if (jt == n - 1) {
#pragma unroll
            for (int nt = 0; nt < 8; ++nt) {
                int kp = jt * 64 + nt * 8 + 2 * t4;
                if (kp     > qpos0)     c[nt][0] = -1e30f;
                if (kp + 1 > qpos0)     c[nt][1] = -1e30f;
                if (kp     > qpos0 + 8) c[nt][2] = -1e30f;
                if (kp + 1 > qpos0 + 8) c[nt][3] = -1e30f;
            }
        }

        // ---- warp-local online softmax ----
        float rm0 = -1e30f, rm1 = -1e30f;
#pragma unroll
        for (int nt = 0; nt < 8; ++nt) {
            rm0 = fmaxf(rm0, fmaxf(c[nt][0], c[nt][1]));
            rm1 = fmaxf(rm1, fmaxf(c[nt][2], c[nt][3]));
        }
        rm0 = fmaxf(rm0, __shfl_xor_sync(FULL, rm0, 1));
        rm0 = fmaxf(rm0, __shfl_xor_sync(FULL, rm0, 2));
        rm1 = fmaxf(rm1, __shfl_xor_sync(FULL, rm1, 1));
        rm1 = fmaxf(rm1, __shfl_xor_sync(FULL, rm1, 2));

        float nm0 = fmaxf(mrow0, rm0);
        float nm1 = fmaxf(mrow1, rm1);
        float corr0 = __expf(mrow0 - nm0); mrow0 = nm0;
        float corr1 = __expf(mrow1 - nm1); mrow1 = nm1;
        float nl0 = nm0 * L2E;
        float nl1 = nm1 * L2E;

#pragma unroll
        for (int nt = 0; nt < 8; ++nt) {
            o[nt][0] *= corr0; o[nt][1] *= corr0;
            o[nt][2] *= corr1; o[nt][3] *= corr1;
        }

        // ---- exp -> PV A-frags + ones-MMA row sums + PV MMA ----
        float ds[4] = {0.f, 0.f, 0.f, 0.f};
#pragma unroll
        for (int kt = 0; kt < 4; ++kt) {
            int ne = 2 * kt, no_ = 2 * kt + 1;
            unsigned aP0 = ex2h2(packh2(c[ne ][1] * L2E - nl0, c[ne ][0] * L2E - nl0));
            unsigned aP1 = ex2h2(packh2(c[ne ][3] * L2E - nl1, c[ne ][2] * L2E - nl1));
            unsigned aP2 = ex2h2(packh2(c[no_][1] * L2E - nl0, c[no_][0] * L2E - nl0));
            unsigned aP3 = ex2h2(packh2(c[no_][3] * L2E - nl1, c[no_][2] * L2E - nl1));
            mma16(ds, aP0, aP1, aP2, aP3, ONES2, ONES2);
#pragma unroll
            for (int nt = 0; nt < 8; ++nt) {
                unsigned b0 = vc[(nt * 8 + g) * P32 + kt * 8 + t4    ];
                unsigned b1 = vc[(nt * 8 + g) * P32 + kt * 8 + t4 + 4];
                mma16(o[nt], aP0, aP1, aP2, aP3, b0, b1);
            }
        }
        lrow0 = lrow0 * corr0 + ds[0];
        lrow1 = lrow1 * corr1 + ds[2];
    }

    // ---- epilogue: unnormalized fp32 partials ----
    float* pa = g_pacc + ((size_t)s * BS + rowbase) * DV;
#pragma unroll
    for (int nt = 0; nt < 8; ++nt) {
        int dc = nt * 8 + 2 * t4;
        *(float2*)(pa + (size_t)r0 * DV + dc)       = make_float2(o[nt][0], o[nt][1]);
        *(float2*)(pa + (size_t)(r0 + 8) * DV + dc) = make_float2(o[nt][2], o[nt][3]);
    }
    if (t4 == 0) {
        g_pm[s * BS + rowbase + r0]     = mrow0;
        g_pl[s * BS + rowbase + r0]     = lrow0;
        g_pm[s * BS + rowbase + r0 + 8] = mrow1;
        g_pl[s * BS + rowbase + r0 + 8] = lrow1;
    }
}

// ---------------------------------------------------------------------------
// Kernel 3b: merge the 4 KV splits -> half2 g_o2  (vectorized: thread = 4 dims)
// ---------------------------------------------------------------------------
__global__ void __launch_bounds__(256) merge_kernel() {
    int tid = blockIdx.x * blockDim.x + threadIdx.x;  // BS*16
    int row = tid >> 4;
    int q4  = tid & 15;   // float4 index within the 64-dim row

    float m[NSPL], l[NSPL];
#pragma unroll
    for (int s = 0; s < NSPL; ++s) {
        m[s] = g_pm[s * BS + row];
        l[s] = g_pl[s * BS + row];
    }
    float M = fmaxf(fmaxf(m[0], m[1]), fmaxf(m[2], m[3]));
    float sc[NSPL];
    float den = 0.f;
#pragma unroll
    for (int s = 0; s < NSPL; ++s) {
        sc[s] = __expf(m[s] - M);
        den += l[s] * sc[s];
    }
    float inv = 1.f / den;

    float4 a = make_float4(0.f, 0.f, 0.f, 0.f);
#pragma unroll
    for (int s = 0; s < NSPL; ++s) {
        float4 p = *(const float4*)(g_pacc + ((size_t)s * BS + row) * DV + q4 * 4);
        a.x += p.x * sc[s]; a.y += p.y * sc[s];
        a.z += p.z * sc[s]; a.w += p.w * sc[s];
    }
    uint2 r;
    r.x = packh2(a.y * inv, a.x * inv);
    r.y = packh2(a.w * inv, a.z * inv);
    *(uint2*)&g_o2[row * 32 + q4 * 2] = r;
}

// ---------------------------------------------------------------------------
// Kernel 4: out[8192,512] = o[8192,64] @ woeff[64,512] + bo  (fp16 mma)
// 256 threads = 8 warps; block = 64 rows x 128 cols; K = 64 single shot.
// ---------------------------------------------------------------------------
__global__ void __launch_bounds__(256) outgemm_mma_kernel(
    const float* __restrict__ bo, float* __restrict__ out)
{
    const int m0 = blockIdx.x * 64;
    const int n0 = blockIdx.y * 128;

    __shared__ unsigned Ao[64 * P32];     // o tile [row][k-half2], pitch 36
    __shared__ unsigned Ws[128 * P32];    // woT tile [n][k-half2], pitch 36

    const int t    = threadIdx.x;
    const int w    = t >> 5;
    const int lane = t & 31;
    const int g    = lane >> 2;
    const int t4   = lane & 3;
    const int rw   = (w & 3) * 16;
    const int cw   = (w >> 2) * 64;

#pragma unroll
    for (int u = 0; u < 2; ++u) {
        int fi = t + u * 256;
        int r  = fi >> 3;
        int c  = (fi & 7) << 2;
        *(float4*)&Ao[r * P32 + c] = *(const float4*)(g_o2 + (size_t)(m0 + r) * 32 + c);
    }
#pragma unroll
    for (int u = 0; u < 4; ++u) {
        int fi = t + u * 256;
        int r  = fi >> 3;
        int c  = (fi & 7) << 2;
        *(float4*)&Ws[r * P32 + c] = *(const float4*)(g_woT2 + (size_t)(n0 + r) * 32 + c);
    }
    __syncthreads();

    float acc[8][4] = {};
#pragma unroll
    for (int kt = 0; kt < 4; ++kt) {
        unsigned a0 = Ao[(rw + g    ) * P32 + kt * 8 + t4    ];
        unsigned a1 = Ao[(rw + g + 8) * P32 + kt * 8 + t4    ];
        unsigned a2 = Ao[(rw + g    ) * P32 + kt * 8 + t4 + 4];
        unsigned a3 = Ao[(rw + g + 8) * P32 + kt * 8 + t4 + 4];
#pragma unroll
        for (int nt = 0; nt < 8; ++nt) {
            unsigned b0 = Ws[(cw + nt * 8 + g) * P32 + kt * 8 + t4    ];
            unsigned b1 = Ws[(cw + nt * 8 + g) * P32 + kt * 8 + t4 + 4];
            mma16(acc[nt], a0, a1, a2, a3, b0, b1);
        }
    }

    const int row0 = m0 + rw + g;
#pragma unroll
    for (int nt = 0; nt < 8; ++nt) {
        int cc = n0 + cw + nt * 8 + 2 * t4;
        float b0 = bo[cc], b1 = bo[cc + 1];
        *(float2*)(out + (size_t)row0 * DD + cc)       = make_float2(acc[nt][0] + b0, acc[nt][1] + b1);
        *(float2*)(out + (size_t)(row0 + 8) * DD + cc) = make_float2(acc[nt][2] + b0, acc[nt][3] + b1);
    }
}

// ---------------------------------------------------------------------------
// Launch
// Inputs: 0 query, 1 key, 2 value(unused), 3 Wq, 4 bq, 5 Wk, 6 bk,
//         7 Wv, 8 bv, 9 Wo, 10 bo
// ---------------------------------------------------------------------------
extern "C" void kernel_launch(void* const* d_in, const int* in_sizes, int n_in,
                              void* d_out, int out_size)
{
    const float* query = (const float*)d_in[0];
    const float* key   = (const float*)d_in[1];
    const float* Wq    = (const float*)d_in[3];
    const float* bq    = (const float*)d_in[4];
    const float* Wk    = (const float*)d_in[5];
    const float* bk    = (const float*)d_in[6];
    const float* Wv    = (const float*)d_in[7];
    const float* bv    = (const float*)d_in[8];
    const float* Wo    = (const float*)d_in[9];
    const float* bo    = (const float*)d_in[10];
    float* out = (float*)d_out;

    woeff_kernel<<<64, 512>>>(Wo);
    proj_mma_kernel<<<dim3(BS / 64, 2), 128>>>(query, key, Wq, bq, Wk, bk, Wv, bv);
    attn_kernel<<<BB * NQT2 * NSPL, 128>>>();
    merge_kernel<<<BS * 16 / 256, 256>>>();
    outgemm_mma_kernel<<<dim3(BS / 64, DD / 128), 256>>>(bo, out);
}

// round 11
// speedup vs baseline: 1.6032x; 1.1641x over previous
#include <cuda_runtime.h>
#include <cuda_fp16.h>
#include <cstdint>

// Problem constants
#define BB 4
#define SS 2048
#define DD 512
#define HH 8
#define DK 64
#define DV 64
#define BS (BB * SS)          // 8192 rows total
#define QT2 64                // query rows per attention block
#define NQT2 (SS / QT2)       // 32 q-tiles per batch
#define NSPL 4                // KV splits per q-tile

// Scratch (device globals: no allocations allowed)
__device__ unsigned g_q2[BS * DK / 2];    // half2: (q@Wq+bq)*0.125, [row][32 u32]
__device__ unsigned g_k2[BS * DK / 2];    // half2: k, [row][32 u32]
__device__ __half   g_vT[BB * DV * SS];   // half, per-batch transposed [dim][seq]
__device__ unsigned g_o2[BS * DV / 2];    // half2: merged attention out
__device__ unsigned g_woT2[DD * DV / 2];  // half2: woeff^T [n][k], [512][32 u32]
__device__ unsigned g_wT[3][DD * DK / 2]; // half2: Wq^T/Wk^T/Wv^T [n][k], [64][256 u32]
// split-KV partials (fp32, unnormalized)
__device__ float    g_pacc[NSPL * BS * DV];  // [split][row][dim]
__device__ float    g_pm[NSPL * BS];
__device__ float    g_pl[NSPL * BS];

// ---------------------------------------------------------------------------
// helpers
// ---------------------------------------------------------------------------
// D(16x8,f32) += A(16x16,f16,row) * B(16x8,f16,col)
__device__ __forceinline__ void mma16(float* c, unsigned a0, unsigned a1,
                                      unsigned a2, unsigned a3,
                                      unsigned b0, unsigned b1) {
    asm volatile(
        "mma.sync.aligned.m16n8k16.row.col.f32.f16.f16.f32 "
        "{%0,%1,%2,%3}, {%4,%5,%6,%7}, {%8,%9}, {%0,%1,%2,%3};\n"
        : "+f"(c[0]), "+f"(c[1]), "+f"(c[2]), "+f"(c[3])
        : "r"(a0), "r"(a1), "r"(a2), "r"(a3), "r"(b0), "r"(b1));
}
__device__ __forceinline__ unsigned packh2(float hi, float lo) {
    unsigned d;
    asm("cvt.rn.f16x2.f32 %0, %1, %2;" : "=r"(d) : "f"(hi), "f"(lo));
    return d;
}
__device__ __forceinline__ unsigned ex2h2(unsigned x) {
    unsigned d;
    asm("ex2.approx.f16x2 %0, %1;" : "=r"(d) : "r"(x));
    return d;
}
__device__ __forceinline__ void cpa16(uint32_t saddr, const void* gaddr) {
    asm volatile("cp.async.cg.shared.global [%0], [%1], 16;\n"
                 :: "r"(saddr), "l"(gaddr));
}
__device__ __forceinline__ void cpa_commit() {
    asm volatile("cp.async.commit_group;\n");
}
__device__ __forceinline__ void cpa_wait0() {
    asm volatile("cp.async.wait_group 0;\n");
}
__device__ __forceinline__ void cpa_wait1() {
    asm volatile("cp.async.wait_group 1;\n");
}

// ---------------------------------------------------------------------------
// Kernel 1: prep. task 0: fold Wo -> half woT [n][k].
//           tasks 1..3: transpose Wq/Wk/Wv -> half [n][k].
// ---------------------------------------------------------------------------
__global__ void prep_kernel(const float* __restrict__ Wo,
                            const float* __restrict__ Wq,
                            const float* __restrict__ Wk,
                            const float* __restrict__ Wv) {
    int idx = blockIdx.x * blockDim.x + threadIdx.x;   // 4 * 32768
    int task = idx >> 15;
    int r    = idx & 32767;
    if (task == 0) {
        int k = r >> 9;          // 0..63
        int n = r & 511;         // 0..511
        float s = 0.f;
#pragma unroll
        for (int h = 0; h < HH; ++h) s += Wo[((h << 6) + k) * DD + n];
        ((__half*)g_woT2)[n * 64 + k] = __float2half(s);
    } else {
        const float* W = (task == 1) ? Wq : (task == 2) ? Wk : Wv;
        int k = r >> 6;          // 0..511
        int n = r & 63;          // 0..63
        ((__half*)g_wT[task - 1])[n * 512 + k] = __float2half(W[r]);
    }
}

// ---------------------------------------------------------------------------
// Kernel 2: fused projections on fp16 tensor cores.
// blockIdx.y: 0 -> q = (query@Wq+bq)*.125 ; 1 -> k = key@Wk+bk AND v = key@Wv+bv.
// Block = 64 rows x 64 cols, K looped in 8 chunks of 64. 128 thr = 4 warps.
// ---------------------------------------------------------------------------
#define P32 36
__global__ void __launch_bounds__(128) proj_mma_kernel(
    const float* __restrict__ query, const float* __restrict__ key,
    const float* __restrict__ bq, const float* __restrict__ bk,
    const float* __restrict__ bv)
{
    const int fused = blockIdx.y;           // 0: q, 1: k+v
    const float* A  = fused ? key : query;
    const int m0 = blockIdx.x * 64;

    __shared__ unsigned As [64 * P32];   // A tile half2 [row][k2]
    __shared__ unsigned W1s[64 * P32];   // W^T tile half2 [n][k2]
    __shared__ unsigned W2s[64 * P32];

    const int t    = threadIdx.x;
    const int w    = t >> 5;
    const int lane = t & 31;
    const int g    = lane >> 2;
    const int t4   = lane & 3;

    const unsigned* w1g = g_wT[fused ? 1 : 0];
    const unsigned* w2g = g_wT[2];

    float c1[8][4] = {};
    float c2[8][4] = {};

    for (int it = 0; it < 8; ++it) {
        const int kk  = it * 64;    // fp32 col offset
        const int kk2 = it * 32;    // u32 (half2) offset
        __syncthreads();
        // A tile: 64 rows x 64 fp32 = 1024 float4, 8/thread; convert to half2
#pragma unroll
        for (int u = 0; u < 8; ++u) {
            int fi = t + u * 128;
            int r  = fi >> 4;
            int c  = fi & 15;             // float4 index within row-chunk
            float4 a4 = *(const float4*)(A + (size_t)(m0 + r) * DD + kk + c * 4);
            uint2 h2;
            h2.x = packh2(a4.y, a4.x);
            h2.y = packh2(a4.w, a4.z);
            *(uint2*)&As[r * P32 + c * 2] = h2;
        }
        // W tiles: 64 n x 32 u32 = 512 float4, 4/thread (raw half copy)
#pragma unroll
        for (int u = 0; u < 4; ++u) {
            int fi = t + u * 128;
            int n  = fi >> 3;
            int c  = fi & 7;
            *(float4*)&W1s[n * P32 + c * 4] =
                *(const float4*)(w1g + (size_t)n * 256 + kk2 + c * 4);
            if (fused)
                *(float4*)&W2s[n * P32 + c * 4] =
                    *(const float4*)(w2g + (size_t)n * 256 + kk2 + c * 4);
        }
        __syncthreads();

#pragma unroll
        for (int kt = 0; kt < 4; ++kt) {
            unsigned a0 = As[(w * 16 + g    ) * P32 + kt * 8 + t4    ];
            unsigned a1 = As[(w * 16 + g + 8) * P32 + kt * 8 + t4    ];
            unsigned a2 = As[(w * 16 + g    ) * P32 + kt * 8 + t4 + 4];
            unsigned a3 = As[(w * 16 + g + 8) * P32 + kt * 8 + t4 + 4];
#pragma unroll
            for (int nt = 0; nt < 8; ++nt) {
                unsigned b0 = W1s[(nt * 8 + g) * P32 + kt * 8 + t4    ];
                unsigned b1 = W1s[(nt * 8 + g) * P32 + kt * 8 + t4 + 4];
                mma16(c1[nt], a0, a1, a2, a3, b0, b1);
            }
            if (fused) {
#pragma unroll
                for (int nt = 0; nt < 8; ++nt) {
                    unsigned b0 = W2s[(nt * 8 + g) * P32 + kt * 8 + t4    ];
                    unsigned b1 = W2s[(nt * 8 + g) * P32 + kt * 8 + t4 + 4];
                    mma16(c2[nt], a0, a1, a2, a3, b0, b1);
                }
            }
        }
    }

    // epilogue -> fp16
    const int r0 = m0 + w * 16 + g;            // global row
    const float* bias1 = fused ? bk : bq;
    unsigned* out1     = fused ? g_k2 : g_q2;
    const float sc     = fused ? 1.0f : 0.125f;
#pragma unroll
    for (int nt = 0; nt < 8; ++nt) {
        int cc = nt * 8 + 2 * t4;
        float b0 = bias1[cc], b1 = bias1[cc + 1];
        out1[r0 * 32 + (cc >> 1)] =
            packh2((c1[nt][1] + b1) * sc, (c1[nt][0] + b0) * sc);
        out1[(r0 + 8) * 32 + (cc >> 1)] =
            packh2((c1[nt][3] + b1) * sc, (c1[nt][2] + b0) * sc);
    }
    if (fused) {
        const int bq_ = r0 >> 11;              // batch
        const int sq  = r0 & 2047;             // seq within batch
#pragma unroll
        for (int nt = 0; nt < 8; ++nt) {
            int cc = nt * 8 + 2 * t4;
            float b0 = bv[cc], b1 = bv[cc + 1];
            __half* base0 = g_vT + ((size_t)bq_ * 64 + cc) * SS;
            __half* base1 = g_vT + ((size_t)bq_ * 64 + cc + 1) * SS;
            base0[sq]     = __float2half(c2[nt][0] + b0);
            base1[sq]     = __float2half(c2[nt][1] + b1);
            base0[sq + 8] = __float2half(c2[nt][2] + b0);
            base1[sq + 8] = __float2half(c2[nt][3] + b1);
        }
    }
}

// ---------------------------------------------------------------------------
// Kernel 3: causal flash attention, fp16, SPLIT-KV (4 splits per q-tile).
// Block = 64 q-rows x quarter of the KV range; 128 threads = 4 warps.
// Emits unnormalized fp32 partials (acc, m, l).
// ---------------------------------------------------------------------------
__global__ void __launch_bounds__(128) attn_kernel() {
    __shared__ unsigned kb[2][64 * P32];
    __shared__ unsigned vb[2][64 * P32];

    const int b    = blockIdx.x & 3;
    const int rest = blockIdx.x >> 2;
    const int it   = (NQT2 - 1) - (rest >> 2);   // longest-first
    const int s    = rest & 3;
    const int n    = it + 1;                     // total KV tiles for this q-tile
    const int jt0  = (s * n) / NSPL;
    const int jt1  = ((s + 1) * n) / NSPL;

    const int t    = threadIdx.x;
    const int w    = t >> 5;
    const int lane = t & 31;
    const int g    = lane >> 2;
    const int t4   = lane & 3;
    const int r0   = w * 16 + g;
    const unsigned FULL = 0xffffffffu;
    const unsigned ONES2 = 0x3C003C00u;
    const float L2E = 1.44269504f;

    const size_t rowbase = (size_t)(b * SS + it * QT2);

    if (jt0 >= jt1) {
        float4 z = make_float4(0.f, 0.f, 0.f, 0.f);
        float* pa = g_pacc + ((size_t)s * BS + rowbase) * DV;
#pragma unroll
        for (int u = 0; u < 8; ++u) ((float4*)pa)[t + u * 128] = z;
        if (t < 64) {
            g_pm[s * BS + rowbase + t] = -1e30f;
            g_pl[s * BS + rowbase + t] = 0.f;
        }
        return;
    }

    // ---- Q A-fragments straight from gmem ----
    const unsigned* qg = g_q2 + rowbase * 32;
    unsigned aq[4][4];
#pragma unroll
    for (int kt = 0; kt < 4; ++kt) {
        aq[kt][0] = qg[(r0    ) * 32 + kt * 8 + t4    ];
        aq[kt][1] = qg[(r0 + 8) * 32 + kt * 8 + t4    ];
        aq[kt][2] = qg[(r0    ) * 32 + kt * 8 + t4 + 4];
        aq[kt][3] = qg[(r0 + 8) * 32 + kt * 8 + t4 + 4];
    }

    const __half* kgp = (const __half*)g_k2 + (size_t)(b * SS) * DK;
    const __half* vgp = g_vT + (size_t)b * 64 * SS;
    const int qpos0 = it * QT2 + r0;

    // prologue: tile jt0 -> buffer 0
    {
        uint32_t kba = (uint32_t)__cvta_generic_to_shared(&kb[0][0]);
        uint32_t vba = (uint32_t)__cvta_generic_to_shared(&vb[0][0]);
        const __half* kg0 = kgp + (size_t)jt0 * 64 * DK;
        const __half* vg0 = vgp + (size_t)jt0 * 64;
#pragma unroll
        for (int u = 0; u < 4; ++u) {
            int fi = t + u * 128;
            int r  = fi >> 3;
            int c  = fi & 7;
            cpa16(kba + (r * P32 + c * 4) * 4, kg0 + (size_t)r * DK + c * 8);
            cpa16(vba + (r * P32 + c * 4) * 4, vg0 + (size_t)r * SS + c * 8);
        }
        cpa_commit();
    }

    float o[8][4] = {};
    float mrow0 = -1e30f, mrow1 = -1e30f;
    float lrow0 = 0.f,    lrow1 = 0.f;

    for (int jt = jt0; jt < jt1; ++jt) {
        const int cur = (jt - jt0) & 1;
        if (jt > jt0) __syncthreads();
        if (jt + 1 < jt1) {
            const int nxt = cur ^ 1;
            uint32_t kba = (uint32_t)__cvta_generic_to_shared(&kb[nxt][0]);
            uint32_t vba = (uint32_t)__cvta_generic_to_shared(&vb[nxt][0]);
            const __half* kgn = kgp + (size_t)(jt + 1) * 64 * DK;
            const __half* vgn = vgp + (size_t)(jt + 1) * 64;
#pragma unroll
            for (int u = 0; u < 4; ++u) {
                int fi = t + u * 128;
                int r  = fi >> 3;
                int c  = fi & 7;
                cpa16(kba + (r * P32 + c * 4) * 4, kgn + (size_t)r * DK + c * 8);
                cpa16(vba + (r * P32 + c * 4) * 4, vgn + (size_t)r * SS + c * 8);
            }
            cpa_commit();
            cpa_wait1();
        } else {
            cpa_wait0();
        }
        __syncthreads();

        const unsigned* kc = &kb[cur][0];
        const unsigned* vc = &vb[cur][0];

        // ---- S = Q K^T ----
        float c[8][4] = {};
#pragma unroll
        for (int kt = 0; kt < 4; ++kt) {
#pragma unroll
            for (int nt = 0; nt < 8; ++nt) {
                unsigned b0 = kc[(nt * 8 + g) * P32 + kt * 8 + t4    ];
                unsigned b1 = kc[(nt * 8 + g) * P32 + kt * 8 + t4 + 4];
                mma16(c[nt], aq[kt][0], aq[kt][1], aq[kt][2], aq[kt][3], b0, b1);
            }
        }

        // ---- causal mask (true diagonal tile only) ----
        if (jt == n - 1) {
#pragma unroll
            for (int nt = 0; nt < 8; ++nt) {
                int kp = jt * 64 + nt * 8 + 2 * t4;
                if (kp     > qpos0)     c[nt][0] = -1e30f;
                if (kp + 1 > qpos0)     c[nt][1] = -1e30f;
                if (kp     > qpos0 + 8) c[nt][2] = -1e30f;
                if (kp + 1 > qpos0 + 8) c[nt][3] = -1e30f;
            }
        }

        // ---- warp-local online softmax ----
        float rm0 = -1e30f, rm1 = -1e30f;
#pragma unroll
        for (int nt = 0; nt < 8; ++nt) {
            rm0 = fmaxf(rm0, fmaxf(c[nt][0], c[nt][1]));
            rm1 = fmaxf(rm1, fmaxf(c[nt][2], c[nt][3]));
        }
        rm0 = fmaxf(rm0, __shfl_xor_sync(FULL, rm0, 1));
        rm0 = fmaxf(rm0, __shfl_xor_sync(FULL, rm0, 2));
        rm1 = fmaxf(rm1, __shfl_xor_sync(FULL, rm1, 1));
        rm1 = fmaxf(rm1, __shfl_xor_sync(FULL, rm1, 2));

        float nm0 = fmaxf(mrow0, rm0);
        float nm1 = fmaxf(mrow1, rm1);
        float corr0 = __expf(mrow0 - nm0); mrow0 = nm0;
        float corr1 = __expf(mrow1 - nm1); mrow1 = nm1;
        float nl0 = nm0 * L2E;
        float nl1 = nm1 * L2E;

#pragma unroll
        for (int nt = 0; nt < 8; ++nt) {
            o[nt][0] *= corr0; o[nt][1] *= corr0;
            o[nt][2] *= corr1; o[nt][3] *= corr1;
        }

        // ---- exp -> PV A-frags + ones-MMA row sums + PV MMA ----
        float ds[4] = {0.f, 0.f, 0.f, 0.f};
#pragma unroll
        for (int kt = 0; kt < 4; ++kt) {
            int ne = 2 * kt, no_ = 2 * kt + 1;
            unsigned aP0 = ex2h2(packh2(c[ne ][1] * L2E - nl0, c[ne ][0] * L2E - nl0));
            unsigned aP1 = ex2h2(packh2(c[ne ][3] * L2E - nl1, c[ne ][2] * L2E - nl1));
            unsigned aP2 = ex2h2(packh2(c[no_][1] * L2E - nl0, c[no_][0] * L2E - nl0));
            unsigned aP3 = ex2h2(packh2(c[no_][3] * L2E - nl1, c[no_][2] * L2E - nl1));
            mma16(ds, aP0, aP1, aP2, aP3, ONES2, ONES2);
#pragma unroll
            for (int nt = 0; nt < 8; ++nt) {
                unsigned b0 = vc[(nt * 8 + g) * P32 + kt * 8 + t4    ];
                unsigned b1 = vc[(nt * 8 + g) * P32 + kt * 8 + t4 + 4];
                mma16(o[nt], aP0, aP1, aP2, aP3, b0, b1);
            }
        }
        lrow0 = lrow0 * corr0 + ds[0];
        lrow1 = lrow1 * corr1 + ds[2];
    }

    // ---- epilogue: unnormalized fp32 partials ----
    float* pa = g_pacc + ((size_t)s * BS + rowbase) * DV;
#pragma unroll
    for (int nt = 0; nt < 8; ++nt) {
        int dc = nt * 8 + 2 * t4;
        *(float2*)(pa + (size_t)r0 * DV + dc)       = make_float2(o[nt][0], o[nt][1]);
        *(float2*)(pa + (size_t)(r0 + 8) * DV + dc) = make_float2(o[nt][2], o[nt][3]);
    }
    if (t4 == 0) {
        g_pm[s * BS + rowbase + r0]     = mrow0;
        g_pl[s * BS + rowbase + r0]     = lrow0;
        g_pm[s * BS + rowbase + r0 + 8] = mrow1;
        g_pl[s * BS + rowbase + r0 + 8] = lrow1;
    }
}

// ---------------------------------------------------------------------------
// Kernel 3b: merge the 4 KV splits -> half2 g_o2 (thread = 1 half2 = 2 dims)
// ---------------------------------------------------------------------------
__global__ void __launch_bounds__(256) merge_kernel() {
    int tid = blockIdx.x * blockDim.x + threadIdx.x;  // BS*32
    int row = tid >> 5;
    int d2  = tid & 31;   // half2 index within the 64-dim row

    float m[NSPL], l[NSPL];
#pragma unroll
    for (int s = 0; s < NSPL; ++s) {
        m[s] = g_pm[s * BS + row];
        l[s] = g_pl[s * BS + row];
    }
    float M = fmaxf(fmaxf(m[0], m[1]), fmaxf(m[2], m[3]));
    float den = 0.f;
    float sc[NSPL];
#pragma unroll
    for (int s = 0; s < NSPL; ++s) {
        sc[s] = __expf(m[s] - M);
        den += l[s] * sc[s];
    }
    float inv = 1.f / den;

    float ax = 0.f, ay = 0.f;
#pragma unroll
    for (int s = 0; s < NSPL; ++s) {
        float2 p = *(const float2*)(g_pacc + ((size_t)s * BS + row) * DV + d2 * 2);
        ax += p.x * sc[s];
        ay += p.y * sc[s];
    }
    g_o2[row * 32 + d2] = packh2(ay * inv, ax * inv);
}

// ---------------------------------------------------------------------------
// Kernel 4: out[8192,512] = o[8192,64] @ woeff[64,512] + bo  (fp16 mma)
// 256 threads = 8 warps; block = 64 rows x 128 cols; K = 64 single shot.
// ---------------------------------------------------------------------------
__global__ void __launch_bounds__(256) outgemm_mma_kernel(
    const float* __restrict__ bo, float* __restrict__ out)
{
    const int m0 = blockIdx.x * 64;
    const int n0 = blockIdx.y * 128;

    __shared__ unsigned Ao[64 * P32];     // o tile [row][k-half2], pitch 36
    __shared__ unsigned Ws[128 * P32];    // woT tile [n][k-half2], pitch 36

    const int t    = threadIdx.x;
    const int w    = t >> 5;
    const int lane = t & 31;
    const int g    = lane >> 2;
    const int t4   = lane & 3;
    const int rw   = (w & 3) * 16;
    const int cw   = (w >> 2) * 64;

#pragma unroll
    for (int u = 0; u < 2; ++u) {
        int fi = t + u * 256;
        int r  = fi >> 3;
        int c  = (fi & 7) << 2;
        *(float4*)&Ao[r * P32 + c] = *(const float4*)(g_o2 + (size_t)(m0 + r) * 32 + c);
    }
#pragma unroll
    for (int u = 0; u < 4; ++u) {
        int fi = t + u * 256;
        int r  = fi >> 3;
        int c  = (fi & 7) << 2;
        *(float4*)&Ws[r * P32 + c] = *(const float4*)(g_woT2 + (size_t)(n0 + r) * 32 + c);
    }
    __syncthreads();

    float acc[8][4] = {};
#pragma unroll
    for (int kt = 0; kt < 4; ++kt) {
        unsigned a0 = Ao[(rw + g    ) * P32 + kt * 8 + t4    ];
        unsigned a1 = Ao[(rw + g + 8) * P32 + kt * 8 + t4    ];
        unsigned a2 = Ao[(rw + g    ) * P32 + kt * 8 + t4 + 4];
        unsigned a3 = Ao[(rw + g + 8) * P32 + kt * 8 + t4 + 4];
#pragma unroll
        for (int nt = 0; nt < 8; ++nt) {
            unsigned b0 = Ws[(cw + nt * 8 + g) * P32 + kt * 8 + t4    ];
            unsigned b1 = Ws[(cw + nt * 8 + g) * P32 + kt * 8 + t4 + 4];
            mma16(acc[nt], a0, a1, a2, a3, b0, b1);
        }
    }

    const int row0 = m0 + rw + g;
#pragma unroll
    for (int nt = 0; nt < 8; ++nt) {
        int cc = n0 + cw + nt * 8 + 2 * t4;
        float b0 = bo[cc], b1 = bo[cc + 1];
        *(float2*)(out + (size_t)row0 * DD + cc)       = make_float2(acc[nt][0] + b0, acc[nt][1] + b1);
        *(float2*)(out + (size_t)(row0 + 8) * DD + cc) = make_float2(acc[nt][2] + b0, acc[nt][3] + b1);
    }
}

// ---------------------------------------------------------------------------
// Launch
// Inputs: 0 query, 1 key, 2 value(unused), 3 Wq, 4 bq, 5 Wk, 6 bk,
//         7 Wv, 8 bv, 9 Wo, 10 bo
// ---------------------------------------------------------------------------
extern "C" void kernel_launch(void* const* d_in, const int* in_sizes, int n_in,
                              void* d_out, int out_size)
{
    const float* query = (const float*)d_in[0];
    const float* key   = (const float*)d_in[1];
    const float* Wq    = (const float*)d_in[3];
    const float* bq    = (const float*)d_in[4];
    const float* Wk    = (const float*)d_in[5];
    const float* bk    = (const float*)d_in[6];
    const float* Wv    = (const float*)d_in[7];
    const float* bv    = (const float*)d_in[8];
    const float* Wo    = (const float*)d_in[9];
    const float* bo    = (const float*)d_in[10];
    float* out = (float*)d_out;

    prep_kernel<<<256, 512>>>(Wo, Wq, Wk, Wv);
    proj_mma_kernel<<<dim3(BS / 64, 2), 128>>>(query, key, bq, bk, bv);
    attn_kernel<<<BB * NQT2 * NSPL, 128>>>();
    merge_kernel<<<BS * 32 / 256, 256>>>();
    outgemm_mma_kernel<<<dim3(BS / 64, DD / 128), 256>>>(bo, out);
}